// round 11
// baseline (speedup 1.0000x reference)
#include <cuda_runtime.h>
#include <cuda_bf16.h>
#include <math.h>
#include <stdint.h>

#define BATCH   16384
#define IN_DIM  1024
#define NODES   1023
#define NODES_PAD 1024
#define LEAVES  1024
#define OUT_DIM 128
#define TREE_DEPTH 10

// ---------------------------------------------------------------------------
// Scratch
// ---------------------------------------------------------------------------
__device__ __nv_bfloat16 g_xs[2][BATCH][IN_DIM];      // hi/lo split of x  (64 MB)
__device__ __nv_bfloat16 g_ws[2][NODES_PAD][IN_DIM];  // hi/lo split of W  (4 MB)
__device__ float g_dec[(size_t)BATCH * NODES_PAD];    // 64 MB decisions
__device__ __nv_bfloat16 g_ps[2][BATCH][LEAVES];      // hi/lo split of leaf probs (64 MB)
__device__ __nv_bfloat16 g_lvs[2][OUT_DIM][LEAVES];   // hi/lo split of leaf_values^T (0.5 MB)
__device__ float g_part[2][BATCH][OUT_DIM];           // split-K partials (16 MB)
__device__ int   g_anymiss[BATCH];

__device__ __forceinline__ uint32_t smem_u32(const void* p) {
    uint32_t a;
    asm("{ .reg .u64 t; cvta.to.shared.u64 t, %1; cvt.u32.u64 %0, t; }" : "=r"(a) : "l"(p));
    return a;
}

// ---------------------------------------------------------------------------
// Unified converter: x (16384 blocks) | W (1024) | leaf_values^T (512)
// ---------------------------------------------------------------------------
#define XB_BLOCKS ((int)((size_t)BATCH * IN_DIM / 4 / 256))        // 16384
#define WB_BLOCKS ((NODES_PAD * IN_DIM / 4 + 255) / 256)           // 1024
#define LV_BLOCKS ((LEAVES * OUT_DIM + 255) / 256)                 // 512

__global__ __launch_bounds__(256) void k_convert_all(const float* __restrict__ x,
                                                     const float* __restrict__ w,
                                                     const float* __restrict__ lv) {
    if (blockIdx.x < XB_BLOCKS) {
        size_t idx = (size_t)blockIdx.x * blockDim.x + threadIdx.x;   // float4 index
        float4 v = ((const float4*)x)[idx];
        bool miss = (v.x != v.x) || (v.y != v.y) || (v.z != v.z) || (v.w != v.w);
        if (miss) atomicExch(&g_anymiss[(int)((idx * 4) / IN_DIM)], 1);
        float f[4] = { (v.x == v.x) ? v.x : 0.f, (v.y == v.y) ? v.y : 0.f,
                       (v.z == v.z) ? v.z : 0.f, (v.w == v.w) ? v.w : 0.f };
        __nv_bfloat16 hi[4], lo[4];
#pragma unroll
        for (int i = 0; i < 4; i++) {
            hi[i] = __float2bfloat16(f[i]);
            lo[i] = __float2bfloat16(f[i] - __bfloat162float(hi[i]));
        }
        *(uint2*)(&g_xs[0][0][0] + idx * 4) = *(uint2*)hi;
        *(uint2*)(&g_xs[1][0][0] + idx * 4) = *(uint2*)lo;
    } else if (blockIdx.x < XB_BLOCKS + WB_BLOCKS) {
        size_t idx = (size_t)(blockIdx.x - XB_BLOCKS) * blockDim.x + threadIdx.x;
        size_t e = idx * 4;
        int n = (int)(e >> 10);
        float f[4] = {0.f, 0.f, 0.f, 0.f};
        if (n < NODES) { float4 v = *(const float4*)&w[e]; f[0] = v.x; f[1] = v.y; f[2] = v.z; f[3] = v.w; }
        __nv_bfloat16 hi[4], lo[4];
#pragma unroll
        for (int i = 0; i < 4; i++) {
            hi[i] = __float2bfloat16(f[i]);
            lo[i] = __float2bfloat16(f[i] - __bfloat162float(hi[i]));
        }
        *(uint2*)(&g_ws[0][0][0] + e) = *(uint2*)hi;
        *(uint2*)(&g_ws[1][0][0] + e) = *(uint2*)lo;
    } else {
        int idx = (blockIdx.x - XB_BLOCKS - WB_BLOCKS) * blockDim.x + threadIdx.x;
        if (idx >= LEAVES * OUT_DIM) return;
        int k = idx >> 7;
        int n = idx & 127;
        float f = lv[idx];
        __nv_bfloat16 hi = __float2bfloat16(f);
        __nv_bfloat16 lo = __float2bfloat16(f - __bfloat162float(hi));
        g_lvs[0][n][k] = hi;
        g_lvs[1][n][k] = lo;
    }
}

// ---------------------------------------------------------------------------
// mma.sync machinery. Warp tile 32x32 (acc 32 regs). BK=64, 3-stage cp.async,
// serialized 3-pass hi/lo. KPS = K-iters per segment (pass); total 3*KPS iters,
// unrolled by 3 so stage indices are compile-time. Runtime k0 for split-K.
//   GEMM1: CTA 128x128, 512 thr, KPS=16, k0=0
//   GEMM2: CTA  64x128, 256 thr, KPS=8, split-K over blockIdx.y
// ---------------------------------------------------------------------------
#define NSTAGES 3
#define BK 64

__device__ __forceinline__ uint32_t swz(uint32_t base, int row, int chunk) {
    return base + row * 128 + ((chunk ^ (row & 7)) << 4);
}

__device__ __forceinline__ void cp16(uint32_t saddr, const void* gaddr) {
    asm volatile("cp.async.cg.shared.global [%0], [%1], 16;" :: "r"(saddr), "l"(gaddr));
}

__device__ __forceinline__ void ldsm_x4(uint32_t addr, uint32_t& r0, uint32_t& r1,
                                        uint32_t& r2, uint32_t& r3) {
    asm volatile("ldmatrix.sync.aligned.m8n8.x4.shared.b16 {%0,%1,%2,%3}, [%4];"
                 : "=r"(r0), "=r"(r1), "=r"(r2), "=r"(r3) : "r"(addr));
}

__device__ __forceinline__ void mma16816(float* d, const uint32_t* a, const uint32_t* b) {
    asm volatile(
        "mma.sync.aligned.m16n8k16.row.col.f32.bf16.bf16.f32 "
        "{%0,%1,%2,%3}, {%4,%5,%6,%7}, {%8,%9}, {%0,%1,%2,%3};"
        : "+f"(d[0]), "+f"(d[1]), "+f"(d[2]), "+f"(d[3])
        : "r"(a[0]), "r"(a[1]), "r"(a[2]), "r"(a[3]), "r"(b[0]), "r"(b[1]));
}

// Per-thread precomputed cp.async offsets
template<int AROWS, int NT>
struct CpOffs {
    static constexpr int ACP = AROWS * 8 / NT;
    static constexpr int BCP = 128 * 8 / NT;
    uint32_t a_s[ACP], b_s[BCP];
    uint32_t a_g[ACP], b_g[BCP];
    __device__ __forceinline__ void init(int m0, int n0, int t) {
#pragma unroll
        for (int i = 0; i < ACP; i++) {
            int idx = i * NT + t;
            int row = idx >> 3, c = idx & 7;
            a_s[i] = swz(0, row, c);
            a_g[i] = (uint32_t)(m0 + row) * 1024u + (uint32_t)c * 8u;
        }
#pragma unroll
        for (int i = 0; i < BCP; i++) {
            int idx = i * NT + t;
            int row = idx >> 3, c = idx & 7;
            b_s[i] = swz(0, row, c);
            b_g[i] = (uint32_t)(n0 + row) * 1024u + (uint32_t)c * 8u;
        }
    }
};

template<int AROWS, int NT, int KPS>
__device__ __forceinline__ void issue_stage_t(
    uint32_t sA, const CpOffs<AROWS, NT>& o,
    const __nv_bfloat16* __restrict__ Ah, const __nv_bfloat16* __restrict__ Al,
    const __nv_bfloat16* __restrict__ Bh, const __nv_bfloat16* __restrict__ Bl,
    int it, uint32_t k0)
{
    const int seg = it / KPS;              // 0,1,2
    const uint32_t kb = (uint32_t)(it & (KPS - 1)) * BK + k0;
    const __nv_bfloat16* Asrc = (seg < 2) ? Ah : Al;   // hi, hi, lo
    const __nv_bfloat16* Bsrc = (seg == 1) ? Bl : Bh;  // hi, lo, hi
    const uint32_t sB = sA + AROWS * 128;
#pragma unroll
    for (int i = 0; i < CpOffs<AROWS, NT>::ACP; i++)
        cp16(sA + o.a_s[i], Asrc + o.a_g[i] + kb);
#pragma unroll
    for (int i = 0; i < CpOffs<AROWS, NT>::BCP; i++)
        cp16(sB + o.b_s[i], Bsrc + o.b_g[i] + kb);
    asm volatile("cp.async.commit_group;" ::: "memory");
}

template<int AROWS, int NT, int MWARPS, int KPS>
__device__ __forceinline__ void gemm_mainloop_t(
    float acc[2][4][4], uint32_t sb,
    const __nv_bfloat16* __restrict__ Ah, const __nv_bfloat16* __restrict__ Al,
    const __nv_bfloat16* __restrict__ Bh, const __nv_bfloat16* __restrict__ Bl,
    int m0, int n0, uint32_t k0, int t)
{
    constexpr int STAGE_B = (AROWS + 128) * 128;
    constexpr int TOT = 3 * KPS;
    const int warp = t >> 5;
    const int lane = t & 31;
    const int wm   = warp & (MWARPS - 1);
    const int wn   = warp / MWARPS;
    const int a_r16 = lane & 15;
    const int lsub  = lane >> 4;
    const int b_row = ((lane >> 3) & 1) * 8 + (lane & 7);

    CpOffs<AROWS, NT> offs;
    offs.init(m0, n0, t);

    issue_stage_t<AROWS, NT, KPS>(sb,           offs, Ah, Al, Bh, Bl, 0, k0);
    issue_stage_t<AROWS, NT, KPS>(sb + STAGE_B, offs, Ah, Al, Bh, Bl, 1, k0);

    for (int ib = 0; ib < KPS; ib++) {
#pragma unroll
        for (int s = 0; s < 3; s++) {
            const int it = ib * 3 + s;     // 0..TOT-1; it % 3 == s
            asm volatile("cp.async.wait_group %0;" :: "n"(NSTAGES - 2) : "memory");
            __syncthreads();

            if (it + 2 < TOT) {
                constexpr int IS_STAGE[3] = {2, 0, 1};   // (s+2)%3
                issue_stage_t<AROWS, NT, KPS>(sb + IS_STAGE[s] * STAGE_B,
                                              offs, Ah, Al, Bh, Bl, it + 2, k0);
            } else {
                asm volatile("cp.async.commit_group;" ::: "memory");
            }

            const uint32_t sA = sb + s * STAGE_B;
            const uint32_t sB = sA + AROWS * 128;

#pragma unroll
            for (int h = 0; h < 4; h++) {
                const int ch = h * 2 + lsub;
                uint32_t a[2][4];
#pragma unroll
                for (int mf = 0; mf < 2; mf++) {
                    int row = wm * 32 + mf * 16 + a_r16;
                    ldsm_x4(swz(sA, row, ch), a[mf][0], a[mf][1], a[mf][2], a[mf][3]);
                }
                uint32_t b[4][2];
#pragma unroll
                for (int nb = 0; nb < 2; nb++) {
                    int row = wn * 32 + nb * 16 + b_row;
                    ldsm_x4(swz(sB, row, ch),
                            b[2 * nb][0], b[2 * nb + 1][0], b[2 * nb][1], b[2 * nb + 1][1]);
                }
#pragma unroll
                for (int mf = 0; mf < 2; mf++)
#pragma unroll
                    for (int nf = 0; nf < 4; nf++)
                        mma16816(acc[mf][nf], a[mf], b[nf]);
            }
        }
    }
}

#define G1_SMEM (NSTAGES * (128 + 128) * 128)   // 98304
#define G2_SMEM (NSTAGES * (64 + 128) * 128)    // 73728

// ---------------------------------------------------------------------------
// GEMM1: logits = x @ W^T + bias -> sigmoid -> g_dec
// ---------------------------------------------------------------------------
__global__ __launch_bounds__(512, 2)
void k_gemm1_mma(const float* __restrict__ bias, const float* __restrict__ temp)
{
    extern __shared__ char smem[];
    const uint32_t sb = smem_u32(smem);
    const int t    = threadIdx.x;
    const int warp = t >> 5;
    const int lane = t & 31;
    const int wm   = warp & 3;
    const int wn   = warp >> 2;
    const int m0   = blockIdx.y * 128;
    const int n0   = blockIdx.x * 128;

    float acc[2][4][4];
#pragma unroll
    for (int i = 0; i < 2; i++)
#pragma unroll
        for (int j = 0; j < 4; j++)
#pragma unroll
            for (int q = 0; q < 4; q++) acc[i][j][q] = 0.0f;

    gemm_mainloop_t<128, 512, 4, 16>(acc, sb, &g_xs[0][0][0], &g_xs[1][0][0],
                                     &g_ws[0][0][0], &g_ws[1][0][0], m0, n0, 0u, t);

    const float invT = 1.0f / __ldg(temp);
    const int lr = lane >> 2;
    const int lc = (lane & 3) * 2;

#pragma unroll
    for (int mf = 0; mf < 2; mf++) {
        const int r0 = m0 + wm * 32 + mf * 16 + lr;
        const int r1 = r0 + 8;
        const int miss0 = g_anymiss[r0];
        const int miss1 = g_anymiss[r1];
        float* __restrict__ p0 = g_dec + (size_t)r0 * NODES_PAD;
        float* __restrict__ p1 = g_dec + (size_t)r1 * NODES_PAD;
#pragma unroll
        for (int nf = 0; nf < 4; nf++) {
            const int n = n0 + wn * 32 + nf * 8 + lc;
            const float bz0 = (n     < NODES) ? __ldg(&bias[n])     : 0.0f;
            const float bz1 = (n + 1 < NODES) ? __ldg(&bias[n + 1]) : 0.0f;
            const float* a4 = acc[mf][nf];
            float2 v0, v1;
            v0.x = miss0 ? 0.5f : 1.0f / (1.0f + __expf(-(a4[0] + bz0) * invT));
            v0.y = miss0 ? 0.5f : 1.0f / (1.0f + __expf(-(a4[1] + bz1) * invT));
            v1.x = miss1 ? 0.5f : 1.0f / (1.0f + __expf(-(a4[2] + bz0) * invT));
            v1.y = miss1 ? 0.5f : 1.0f / (1.0f + __expf(-(a4[3] + bz1) * invT));
            *(float2*)(p0 + n) = v0;
            *(float2*)(p1 + n) = v1;
        }
    }
}

// ---------------------------------------------------------------------------
// GEMM2: split-K partials. blockIdx.x = m-tile (0..255), blockIdx.y = split.
// Each split covers K range [split*512, split*512+512) per hi/lo pass.
// ---------------------------------------------------------------------------
__global__ __launch_bounds__(256, 3)
void k_gemm2_mma()
{
    extern __shared__ char smem[];
    const uint32_t sb = smem_u32(smem);
    const int t    = threadIdx.x;
    const int warp = t >> 5;
    const int lane = t & 31;
    const int wm   = warp & 1;
    const int wn   = warp >> 1;
    const int m0   = blockIdx.x * 64;
    const int split = blockIdx.y;
    const uint32_t k0 = split * 512u;

    float acc[2][4][4];
#pragma unroll
    for (int i = 0; i < 2; i++)
#pragma unroll
        for (int j = 0; j < 4; j++)
#pragma unroll
            for (int q = 0; q < 4; q++) acc[i][j][q] = 0.0f;

    gemm_mainloop_t<64, 256, 2, 8>(acc, sb, &g_ps[0][0][0], &g_ps[1][0][0],
                                   &g_lvs[0][0][0], &g_lvs[1][0][0], m0, 0, k0, t);

    const int lr = lane >> 2;
    const int lc = (lane & 3) * 2;
    float* __restrict__ base = &g_part[split][0][0];
#pragma unroll
    for (int mf = 0; mf < 2; mf++) {
        const int r0 = m0 + wm * 32 + mf * 16 + lr;
        const int r1 = r0 + 8;
        float* __restrict__ p0 = base + (size_t)r0 * OUT_DIM;
        float* __restrict__ p1 = base + (size_t)r1 * OUT_DIM;
#pragma unroll
        for (int nf = 0; nf < 4; nf++) {
            const int n = wn * 32 + nf * 8 + lc;
            const float* a4 = acc[mf][nf];
            *(float2*)(p0 + n) = make_float2(a4[0], a4[1]);
            *(float2*)(p1 + n) = make_float2(a4[2], a4[3]);
        }
    }
}

// Reduce: out = part0 + part1 (float4, fully coalesced)
__global__ __launch_bounds__(256) void k_reduce(float* __restrict__ out) {
    size_t i = (size_t)blockIdx.x * blockDim.x + threadIdx.x;   // float4 index
    const float4 a = ((const float4*)&g_part[0][0][0])[i];
    const float4 b = ((const float4*)&g_part[1][0][0])[i];
    ((float4*)out)[i] = make_float4(a.x + b.x, a.y + b.y, a.z + b.z, a.w + b.w);
}

// ---------------------------------------------------------------------------
// Routing kernel — closed form, zero syncs (see round 10)
// ---------------------------------------------------------------------------
__global__ __launch_bounds__(128) void k_route() {
    const int row = blockIdx.x;
    const int tid = threadIdx.x;           // 0..127
    const float* __restrict__ drow = g_dec + (size_t)row * NODES_PAD;

    float pre = 1.0f;
#pragma unroll
    for (int L = 0; L < 7; L++) {
        int node = (1 << L) - 1 + (tid & ((1 << L) - 1));
        float d = __ldg(&drow[node]);
        pre *= ((tid >> L) & 1) ? (1.0f - d) : d;
    }
    const float d7 = __ldg(&drow[127 + tid]);
    float d8[2];
#pragma unroll
    for (int i = 0; i < 2; i++) d8[i] = __ldg(&drow[255 + tid + 128 * i]);
    float d9[4];
#pragma unroll
    for (int i = 0; i < 4; i++) d9[i] = __ldg(&drow[511 + tid + 128 * i]);

    __nv_bfloat16* __restrict__ ph = &g_ps[0][row][0];
    __nv_bfloat16* __restrict__ pl = &g_ps[1][row][0];
#pragma unroll
    for (int q = 0; q < 8; q++) {
        float p = pre;
        p *= (q & 1)        ? (1.0f - d7)        : d7;
        p *= ((q >> 1) & 1) ? (1.0f - d8[q & 1]) : d8[q & 1];
        p *= ((q >> 2) & 1) ? (1.0f - d9[q & 3]) : d9[q & 3];
        const int j = tid + 128 * q;
        __nv_bfloat16 h = __float2bfloat16(p);
        ph[j] = h;
        pl[j] = __float2bfloat16(p - __bfloat162float(h));
    }
}

// ---------------------------------------------------------------------------
// Launch
// ---------------------------------------------------------------------------
extern "C" void kernel_launch(void* const* d_in, const int* in_sizes, int n_in,
                              void* d_out, int out_size)
{
    const float* x    = (const float*)d_in[0];
    const float* w    = (const float*)d_in[1];
    const float* bias = (const float*)d_in[2];
    const float* lv   = (const float*)d_in[3];
    const float* temp = (const float*)d_in[4];
    float* out = (float*)d_out;

    static int smem_set = 0;
    if (!smem_set) {
        cudaFuncSetAttribute(k_gemm1_mma, cudaFuncAttributeMaxDynamicSharedMemorySize, G1_SMEM);
        cudaFuncSetAttribute(k_gemm2_mma, cudaFuncAttributeMaxDynamicSharedMemorySize, G2_SMEM);
        smem_set = 1;
    }

    k_convert_all<<<XB_BLOCKS + WB_BLOCKS + LV_BLOCKS, 256>>>(x, w, lv);
    {
        dim3 grid(NODES_PAD / 128, BATCH / 128);   // (8, 128)
        k_gemm1_mma<<<grid, 512, G1_SMEM>>>(bias, temp);
    }
    k_route<<<BATCH, 128>>>();
    {
        dim3 grid(BATCH / 64, 2);                  // (256, 2) split-K
        k_gemm2_mma<<<grid, 256, G2_SMEM>>>();
    }
    k_reduce<<<(BATCH * OUT_DIM / 4) / 256, 256>>>(out);
}